// round 1
// baseline (speedup 1.0000x reference)
#include <cuda_runtime.h>
#include <cstdint>

// Problem constants (shapes fixed by the dataset)
#define DCOL   901
#define NMAX   50048
#define FEAT   128

// Scratch (no allocation allowed -> __device__ globals)
__device__ float  g_w128[8][128];   // combined 128-d weight vectors
__device__ float  g_spa[8][4];      // combined spatial (4-d) weights
__device__ float  g_spk[8][3];      // speaker LUT contribution
__device__ float  g_cst[8];         // constants (biases folded, incl. edge bias for 'a' vecs)
__device__ float4 g_a[NMAX];        // per-node dst-side scalars (face0,face1,body0,body1)
__device__ float4 g_b[NMAX];        // per-node src-side scalars
__device__ uint4  g_key[NMAX];      // ordered-uint max keys, 0 = "no edge" sentinel

// vec index v in 0..7:  blockSel=v>>2 (0=face,1=body), kind=(v>>1)&1 (0=a,1=b), c=v&1
__global__ void precompute_kernel(
    const float* __restrict__ f1_w, const float* __restrict__ f1_b,
    const float* __restrict__ f2_w, const float* __restrict__ f2_b,
    const float* __restrict__ fe_w, const float* __restrict__ fe_b,
    const float* __restrict__ g1_w, const float* __restrict__ g1_b,
    const float* __restrict__ g2_w, const float* __restrict__ g2_b,
    const float* __restrict__ ge_w, const float* __restrict__ ge_b,
    const float* __restrict__ speaker_w, const float* __restrict__ speaker_b,
    const float* __restrict__ spatial_w, const float* __restrict__ spatial_b)
{
    int v = blockIdx.x;
    int body = v >> 2;
    int kind = (v >> 1) & 1;   // 0 = a (dst side), 1 = b (src side)
    int c = v & 1;
    const float* W1 = body ? g1_w : f1_w;
    const float* B1 = body ? g1_b : f1_b;
    const float* W2 = body ? g2_w : f2_w;
    const float* B2 = body ? g2_b : f2_b;
    const float* EW = body ? ge_w : fe_w;
    const float* EB = body ? ge_b : fe_b;

    __shared__ float u[64], Su[16], Pu[16];
    int t = threadIdx.x;
    if (t < 64) {
        float lo = EW[t * 2 + c];          // W[:64, c]
        float hi = EW[(64 + t) * 2 + c];   // W[64:, c]
        u[t] = kind ? hi : (lo - hi);
    }
    __syncthreads();

    // w128[v][t] = sum_k (f1_w[t,k] + f2_w[t,k]) * u[k]
    {
        float s = 0.f;
        #pragma unroll 8
        for (int k = 0; k < 64; k++)
            s += (W1[t * 64 + k] + W2[t * 64 + k]) * u[k];
        g_w128[v][t] = s;
    }
    if (t < 16) {            // Su: speaker rows of f2_w (rows 128..143)
        float s = 0.f;
        for (int k = 0; k < 64; k++) s += W2[(128 + t) * 64 + k] * u[k];
        Su[t] = s;
    } else if (t < 32) {     // Pu: spatial rows (rows 144..159)
        int m = t - 16;
        float s = 0.f;
        for (int k = 0; k < 64; k++) s += W2[(144 + m) * 64 + k] * u[k];
        Pu[m] = s;
    }
    __syncthreads();

    if (t < 4) {             // spatial_w (4,16) projected by Pu
        float s = 0.f;
        for (int m = 0; m < 16; m++) s += spatial_w[t * 16 + m] * Pu[m];
        g_spa[v][t] = s;
    } else if (t < 7) {      // speaker LUT: speaker_w row r projected by Su
        int r = t - 4;
        float s = 0.f;
        for (int m = 0; m < 16; m++) s += speaker_w[r * 16 + m] * Su[m];
        g_spk[v][r] = s;
    } else if (t == 7) {     // constants
        float s = 0.f;
        for (int k = 0; k < 64; k++) s += (B1[k] + B2[k]) * u[k];
        for (int m = 0; m < 16; m++) s += speaker_b[m] * Su[m] + spatial_b[m] * Pu[m];
        if (kind == 0) s += EB[c];   // edge bias folds into the dst-side scalar
        g_cst[v] = s;
    }
}

__global__ void init_keys_kernel(int N)
{
    int i = blockIdx.x * blockDim.x + threadIdx.x;
    if (i < N) g_key[i] = make_uint4(0u, 0u, 0u, 0u);
}

// one warp per node: 8 dot products of length 128
__global__ void node_kernel(const float* __restrict__ x, int N)
{
    __shared__ float sW[8][128];
    int t = threadIdx.x;
    #pragma unroll
    for (int i = t; i < 1024; i += 256)
        sW[i >> 7][i & 127] = g_w128[i >> 7][i & 127];
    __syncthreads();

    int warp = t >> 5, lane = t & 31;
    int node = blockIdx.x * 8 + warp;
    if (node >= N) return;

    const float* row = x + (size_t)node * DCOL;
    float acc[8] = {0.f, 0.f, 0.f, 0.f, 0.f, 0.f, 0.f, 0.f};
    #pragma unroll
    for (int it = 0; it < 4; it++) {
        int k = lane + it * 32;
        float xf = row[k];
        float xb = row[FEAT + k];
        acc[0] += xf * sW[0][k]; acc[1] += xf * sW[1][k];
        acc[2] += xf * sW[2][k]; acc[3] += xf * sW[3][k];
        acc[4] += xb * sW[4][k]; acc[5] += xb * sW[5][k];
        acc[6] += xb * sW[6][k]; acc[7] += xb * sW[7][k];
    }
    #pragma unroll
    for (int off = 16; off > 0; off >>= 1) {
        #pragma unroll
        for (int v = 0; v < 8; v++)
            acc[v] += __shfl_xor_sync(0xffffffffu, acc[v], off);
    }
    if (lane == 0) {
        float s0 = row[896], s1 = row[897], s2 = row[898], s3 = row[899];
        int idx = (int)row[900] - 1;
        idx = idx < 0 ? 0 : (idx > 2 ? 2 : idx);
        float val[8];
        #pragma unroll
        for (int v = 0; v < 8; v++) {
            val[v] = acc[v] + g_cst[v] + g_spk[v][idx]
                   + s0 * g_spa[v][0] + s1 * g_spa[v][1]
                   + s2 * g_spa[v][2] + s3 * g_spa[v][3];
        }
        g_a[node] = make_float4(val[0], val[1], val[4], val[5]); // face a0,a1, body a0,a1
        g_b[node] = make_float4(val[2], val[3], val[6], val[7]); // face b0,b1, body b0,b1
    }
}

__device__ __forceinline__ unsigned f2key(float f)
{
    unsigned u = __float_as_uint(f);
    return (u & 0x80000000u) ? ~u : (u | 0x80000000u);
}
__device__ __forceinline__ float key2f(unsigned k)
{
    unsigned u = (k & 0x80000000u) ? (k ^ 0x80000000u) : ~k;
    return __uint_as_float(u);
}

__global__ void edge_kernel(const int* __restrict__ ei, const int* __restrict__ ea, int E)
{
    int e = blockIdx.x * blockDim.x + threadIdx.x;
    if (e >= E) return;
    int attr = ea[e];
    if (attr != 111 && attr != 0) return;
    int s = ei[e];
    int d = ei[E + e];
    float4 bv = g_b[s];
    unsigned* kp = (unsigned*)&g_key[d];
    atomicMax(kp + 0, f2key(bv.x));
    atomicMax(kp + 1, f2key(bv.y));
    atomicMax(kp + 2, f2key(bv.z));
    atomicMax(kp + 3, f2key(bv.w));
}

__global__ void final_kernel(float* __restrict__ out, int N)
{
    int i = blockIdx.x * blockDim.x + threadIdx.x;
    if (i >= N) return;
    uint4 k = g_key[i];
    float4 a = g_a[i];
    float o0 = 0.f, o1 = 0.f;
    if (k.x) o0 += a.x + key2f(k.x);   // face ch0
    if (k.z) o0 += a.z + key2f(k.z);   // body ch0
    if (k.y) o1 += a.y + key2f(k.y);   // face ch1
    if (k.w) o1 += a.w + key2f(k.w);   // body ch1
    out[i * 2 + 0] = o0;
    out[i * 2 + 1] = o1;
}

extern "C" void kernel_launch(void* const* d_in, const int* in_sizes, int n_in,
                              void* d_out, int out_size)
{
    const float* x         = (const float*)d_in[0];
    const int*   ei        = (const int*)d_in[1];
    const int*   ea        = (const int*)d_in[2];
    const float* speaker_w = (const float*)d_in[3];
    const float* speaker_b = (const float*)d_in[4];
    const float* spatial_w = (const float*)d_in[5];
    const float* spatial_b = (const float*)d_in[6];
    const float* f1_w = (const float*)d_in[7];
    const float* f1_b = (const float*)d_in[8];
    const float* f2_w = (const float*)d_in[9];
    const float* f2_b = (const float*)d_in[10];
    const float* fe_w = (const float*)d_in[11];
    const float* fe_b = (const float*)d_in[12];
    const float* g1_w = (const float*)d_in[13];
    const float* g1_b = (const float*)d_in[14];
    const float* g2_w = (const float*)d_in[15];
    const float* g2_b = (const float*)d_in[16];
    const float* ge_w = (const float*)d_in[17];
    const float* ge_b = (const float*)d_in[18];

    int N = in_sizes[0] / DCOL;
    int E = in_sizes[2];

    precompute_kernel<<<8, 128>>>(f1_w, f1_b, f2_w, f2_b, fe_w, fe_b,
                                  g1_w, g1_b, g2_w, g2_b, ge_w, ge_b,
                                  speaker_w, speaker_b, spatial_w, spatial_b);
    init_keys_kernel<<<(N + 255) / 256, 256>>>(N);
    node_kernel<<<(N + 7) / 8, 256>>>(x, N);
    edge_kernel<<<(E + 255) / 256, 256>>>(ei, ea, E);
    final_kernel<<<(N + 255) / 256, 256>>>((float*)d_out, N);
}

// round 3
// speedup vs baseline: 1.2997x; 1.2997x over previous
#include <cuda_runtime.h>
#include <cstdint>

#define DCOL   901
#define NMAX   50048
#define FEAT   128

__device__ float  g_w128[8][128];
__device__ float  g_spa[8][4];
__device__ float  g_spk[8][3];
__device__ float  g_cst[8];
__device__ float4 g_a[NMAX];
__device__ float4 g_b[NMAX];
__device__ uint4  g_key[NMAX];

// vec index v: body=v>>2, kind=(v>>1)&1 (0=a dst-side, 1=b src-side), c=v&1
// One block per v, 512 threads. Warp w handles rows r = w + 16*j, j=0..9 (160 rows).
__global__ void precompute_kernel(
    const float* __restrict__ f1_w, const float* __restrict__ f1_b,
    const float* __restrict__ f2_w, const float* __restrict__ f2_b,
    const float* __restrict__ fe_w, const float* __restrict__ fe_b,
    const float* __restrict__ g1_w, const float* __restrict__ g1_b,
    const float* __restrict__ g2_w, const float* __restrict__ g2_b,
    const float* __restrict__ ge_w, const float* __restrict__ ge_b,
    const float* __restrict__ speaker_w, const float* __restrict__ speaker_b,
    const float* __restrict__ spatial_w, const float* __restrict__ spatial_b)
{
    int v = blockIdx.x;
    int body = v >> 2;
    int kind = (v >> 1) & 1;
    int c = v & 1;
    const float* W1 = body ? g1_w : f1_w;
    const float* B1 = body ? g1_b : f1_b;
    const float* W2 = body ? g2_w : f2_w;
    const float* B2 = body ? g2_b : f2_b;
    const float* EW = body ? ge_w : fe_w;
    const float* EB = body ? ge_b : fe_b;

    __shared__ float u[64], Su[16], Pu[16];
    int t = threadIdx.x;
    int warp = t >> 5, lane = t & 31;
    if (t < 64) {
        float lo = EW[t * 2 + c];
        float hi = EW[(64 + t) * 2 + c];
        u[t] = kind ? hi : (lo - hi);
    }
    __syncthreads();

    // 160 row-dots of length 64: warp per row, 2 elems per lane
    #pragma unroll
    for (int j = 0; j < 10; j++) {
        int r = warp + 16 * j;
        int k0 = lane, k1 = lane + 32;
        float s;
        if (r < 128) {
            s = (W1[r * 64 + k0] + W2[r * 64 + k0]) * u[k0]
              + (W1[r * 64 + k1] + W2[r * 64 + k1]) * u[k1];
        } else {
            s = W2[r * 64 + k0] * u[k0] + W2[r * 64 + k1] * u[k1];
        }
        #pragma unroll
        for (int off = 16; off > 0; off >>= 1)
            s += __shfl_xor_sync(0xffffffffu, s, off);
        if (lane == 0) {
            if (r < 128)      g_w128[v][r] = s;
            else if (r < 144) Su[r - 128] = s;
            else              Pu[r - 144] = s;
        }
    }
    __syncthreads();

    if (t < 4) {
        float s = 0.f;
        for (int m = 0; m < 16; m++) s += spatial_w[t * 16 + m] * Pu[m];
        g_spa[v][t] = s;
    } else if (t < 7) {
        int r = t - 4;
        float s = 0.f;
        for (int m = 0; m < 16; m++) s += speaker_w[r * 16 + m] * Su[m];
        g_spk[v][r] = s;
    } else if (t == 7) {
        float s = 0.f;
        for (int k = 0; k < 64; k++) s += (B1[k] + B2[k]) * u[k];
        for (int m = 0; m < 16; m++) s += speaker_b[m] * Su[m] + spatial_b[m] * Pu[m];
        if (kind == 0) s += EB[c];
        g_cst[v] = s;
    }
}

// 512 threads = 16 warps = 16 nodes per block. Also zeroes g_key.
__global__ void node_kernel(const float* __restrict__ x, int N)
{
    __shared__ float sW[8][128];
    int t = threadIdx.x;
    #pragma unroll
    for (int i = t; i < 1024; i += 512)
        sW[i >> 7][i & 127] = g_w128[i >> 7][i & 127];
    __syncthreads();

    int warp = t >> 5, lane = t & 31;
    int node = blockIdx.x * 16 + warp;
    if (node >= N) return;

    if (lane == 1) g_key[node] = make_uint4(0u, 0u, 0u, 0u);

    const float* row = x + (size_t)node * DCOL;
    // tail loads overlap with main loop (lanes 0..4)
    float tail = (lane < 5) ? row[896 + lane] : 0.f;

    float acc[8] = {0.f, 0.f, 0.f, 0.f, 0.f, 0.f, 0.f, 0.f};
    #pragma unroll
    for (int it = 0; it < 4; it++) {
        int k = lane + it * 32;
        float xf = row[k];
        float xb = row[FEAT + k];
        acc[0] += xf * sW[0][k]; acc[1] += xf * sW[1][k];
        acc[2] += xf * sW[2][k]; acc[3] += xf * sW[3][k];
        acc[4] += xb * sW[4][k]; acc[5] += xb * sW[5][k];
        acc[6] += xb * sW[6][k]; acc[7] += xb * sW[7][k];
    }
    #pragma unroll
    for (int off = 16; off > 0; off >>= 1) {
        #pragma unroll
        for (int v = 0; v < 8; v++)
            acc[v] += __shfl_xor_sync(0xffffffffu, acc[v], off);
    }
    float s0 = __shfl_sync(0xffffffffu, tail, 0);
    float s1 = __shfl_sync(0xffffffffu, tail, 1);
    float s2 = __shfl_sync(0xffffffffu, tail, 2);
    float s3 = __shfl_sync(0xffffffffu, tail, 3);
    float s4 = __shfl_sync(0xffffffffu, tail, 4);
    if (lane == 0) {
        int idx = (int)s4 - 1;
        idx = idx < 0 ? 0 : (idx > 2 ? 2 : idx);
        float val[8];
        #pragma unroll
        for (int v = 0; v < 8; v++) {
            val[v] = acc[v] + g_cst[v] + g_spk[v][idx]
                   + s0 * g_spa[v][0] + s1 * g_spa[v][1]
                   + s2 * g_spa[v][2] + s3 * g_spa[v][3];
        }
        g_a[node] = make_float4(val[0], val[1], val[4], val[5]);
        g_b[node] = make_float4(val[2], val[3], val[6], val[7]);
    }
}

__device__ __forceinline__ unsigned f2key(float f)
{
    unsigned u = __float_as_uint(f);
    return (u & 0x80000000u) ? ~u : (u | 0x80000000u);
}
__device__ __forceinline__ float key2f(unsigned k)
{
    unsigned u = (k & 0x80000000u) ? (k ^ 0x80000000u) : ~k;
    return __uint_as_float(u);
}

// 2 edges per thread; check current max before issuing the RED (keys monotone ->
// skipping when k <= observed is race-safe).
__global__ void edge_kernel(const int* __restrict__ ei, const int* __restrict__ ea, int E)
{
    int i = blockIdx.x * blockDim.x + threadIdx.x;
    int e0 = 2 * i, e1 = 2 * i + 1;
    if (e0 >= E) return;

    int s0 = ei[e0], d0 = ei[E + e0], a0 = ea[e0];
    bool v0 = (a0 == 111) | (a0 == 0);
    bool has1 = (e1 < E);
    int s1 = 0, d1 = 0, a1 = -1;
    if (has1) { s1 = ei[e1]; d1 = ei[E + e1]; a1 = ea[e1]; }
    bool v1 = has1 && ((a1 == 111) | (a1 == 0));

    float4 b0, b1; uint4 c0, c1;
    if (v0) { b0 = g_b[s0]; c0 = g_key[d0]; }
    if (v1) { b1 = g_b[s1]; c1 = g_key[d1]; }

    if (v0) {
        unsigned* kp = (unsigned*)&g_key[d0];
        unsigned k;
        k = f2key(b0.x); if (k > c0.x) atomicMax(kp + 0, k);
        k = f2key(b0.y); if (k > c0.y) atomicMax(kp + 1, k);
        k = f2key(b0.z); if (k > c0.z) atomicMax(kp + 2, k);
        k = f2key(b0.w); if (k > c0.w) atomicMax(kp + 3, k);
    }
    if (v1) {
        unsigned* kp = (unsigned*)&g_key[d1];
        unsigned k;
        k = f2key(b1.x); if (k > c1.x) atomicMax(kp + 0, k);
        k = f2key(b1.y); if (k > c1.y) atomicMax(kp + 1, k);
        k = f2key(b1.z); if (k > c1.z) atomicMax(kp + 2, k);
        k = f2key(b1.w); if (k > c1.w) atomicMax(kp + 3, k);
    }
}

__global__ void final_kernel(float* __restrict__ out, int N)
{
    int i = blockIdx.x * blockDim.x + threadIdx.x;
    if (i >= N) return;
    uint4 k = g_key[i];
    float4 a = g_a[i];
    float o0 = 0.f, o1 = 0.f;
    if (k.x) o0 += a.x + key2f(k.x);
    if (k.z) o0 += a.z + key2f(k.z);
    if (k.y) o1 += a.y + key2f(k.y);
    if (k.w) o1 += a.w + key2f(k.w);
    out[i * 2 + 0] = o0;
    out[i * 2 + 1] = o1;
}

extern "C" void kernel_launch(void* const* d_in, const int* in_sizes, int n_in,
                              void* d_out, int out_size)
{
    const float* x         = (const float*)d_in[0];
    const int*   ei        = (const int*)d_in[1];
    const int*   ea        = (const int*)d_in[2];
    const float* speaker_w = (const float*)d_in[3];
    const float* speaker_b = (const float*)d_in[4];
    const float* spatial_w = (const float*)d_in[5];
    const float* spatial_b = (const float*)d_in[6];
    const float* f1_w = (const float*)d_in[7];
    const float* f1_b = (const float*)d_in[8];
    const float* f2_w = (const float*)d_in[9];
    const float* f2_b = (const float*)d_in[10];
    const float* fe_w = (const float*)d_in[11];
    const float* fe_b = (const float*)d_in[12];
    const float* g1_w = (const float*)d_in[13];
    const float* g1_b = (const float*)d_in[14];
    const float* g2_w = (const float*)d_in[15];
    const float* g2_b = (const float*)d_in[16];
    const float* ge_w = (const float*)d_in[17];
    const float* ge_b = (const float*)d_in[18];

    int N = in_sizes[0] / DCOL;
    int E = in_sizes[2];

    precompute_kernel<<<8, 512>>>(f1_w, f1_b, f2_w, f2_b, fe_w, fe_b,
                                  g1_w, g1_b, g2_w, g2_b, ge_w, ge_b,
                                  speaker_w, speaker_b, spatial_w, spatial_b);
    node_kernel<<<(N + 15) / 16, 512>>>(x, N);
    int pairs = (E + 1) / 2;
    edge_kernel<<<(pairs + 255) / 256, 256>>>(ei, ea, E);
    final_kernel<<<(N + 255) / 256, 256>>>((float*)d_out, N);
}

// round 7
// speedup vs baseline: 1.4588x; 1.1224x over previous
#include <cuda_runtime.h>
#include <cstdint>

#define DCOL   901
#define NMAX   50048
#define FEAT   128

__device__ float  g_w128[8][128];
__device__ float  g_spa[8][4];
__device__ float  g_spk[8][3];
__device__ float  g_cst[8];
__device__ float4 g_a[NMAX];
__device__ float4 g_b[NMAX];
__device__ uint4  g_key[NMAX];

// vec index v: body=v>>2, kind=(v>>1)&1 (0=a dst-side, 1=b src-side), c=v&1
__global__ void precompute_kernel(
    const float* __restrict__ f1_w, const float* __restrict__ f1_b,
    const float* __restrict__ f2_w, const float* __restrict__ f2_b,
    const float* __restrict__ fe_w, const float* __restrict__ fe_b,
    const float* __restrict__ g1_w, const float* __restrict__ g1_b,
    const float* __restrict__ g2_w, const float* __restrict__ g2_b,
    const float* __restrict__ ge_w, const float* __restrict__ ge_b,
    const float* __restrict__ speaker_w, const float* __restrict__ speaker_b,
    const float* __restrict__ spatial_w, const float* __restrict__ spatial_b)
{
    int v = blockIdx.x;
    int body = v >> 2;
    int kind = (v >> 1) & 1;
    int c = v & 1;
    const float* W1 = body ? g1_w : f1_w;
    const float* B1 = body ? g1_b : f1_b;
    const float* W2 = body ? g2_w : f2_w;
    const float* B2 = body ? g2_b : f2_b;
    const float* EW = body ? ge_w : fe_w;
    const float* EB = body ? ge_b : fe_b;

    __shared__ float u[64], Su[16], Pu[16];
    int t = threadIdx.x;
    int warp = t >> 5, lane = t & 31;
    if (t < 64) {
        float lo = EW[t * 2 + c];
        float hi = EW[(64 + t) * 2 + c];
        u[t] = kind ? hi : (lo - hi);
    }
    __syncthreads();

    #pragma unroll
    for (int j = 0; j < 10; j++) {
        int r = warp + 16 * j;
        int k0 = lane, k1 = lane + 32;
        float s;
        if (r < 128) {
            s = (W1[r * 64 + k0] + W2[r * 64 + k0]) * u[k0]
              + (W1[r * 64 + k1] + W2[r * 64 + k1]) * u[k1];
        } else {
            s = W2[r * 64 + k0] * u[k0] + W2[r * 64 + k1] * u[k1];
        }
        #pragma unroll
        for (int off = 16; off > 0; off >>= 1)
            s += __shfl_xor_sync(0xffffffffu, s, off);
        if (lane == 0) {
            if (r < 128)      g_w128[v][r] = s;
            else if (r < 144) Su[r - 128] = s;
            else              Pu[r - 144] = s;
        }
    }
    __syncthreads();

    if (t < 4) {
        float s = 0.f;
        for (int m = 0; m < 16; m++) s += spatial_w[t * 16 + m] * Pu[m];
        g_spa[v][t] = s;
    } else if (t < 7) {
        int r = t - 4;
        float s = 0.f;
        for (int m = 0; m < 16; m++) s += speaker_w[r * 16 + m] * Su[m];
        g_spk[v][r] = s;
    } else if (t == 7) {
        float s = 0.f;
        for (int k = 0; k < 64; k++) s += (B1[k] + B2[k]) * u[k];
        for (int m = 0; m < 16; m++) s += speaker_b[m] * Su[m] + spatial_b[m] * Pu[m];
        if (kind == 0) s += EB[c];
        g_cst[v] = s;
    }
}

// 512 threads = 16 warps; each warp processes 2 adjacent nodes (32 nodes/block).
// Also zeroes g_key.
__global__ void __launch_bounds__(512) node_kernel(const float* __restrict__ x, int N)
{
    __shared__ float sW[8][128];
    int t = threadIdx.x;
    #pragma unroll
    for (int i = t; i < 1024; i += 512)
        sW[i >> 7][i & 127] = g_w128[i >> 7][i & 127];
    __syncthreads();

    int warp = t >> 5, lane = t & 31;
    int n0 = blockIdx.x * 32 + warp * 2;
    int n1 = n0 + 1;
    bool has0 = n0 < N, has1 = n1 < N;
    if (!has0) return;

    if (lane == 1) g_key[n0] = make_uint4(0u, 0u, 0u, 0u);
    if (lane == 2 && has1) g_key[n1] = make_uint4(0u, 0u, 0u, 0u);

    const float* rowA = x + (size_t)n0 * DCOL;
    const float* rowB = x + (size_t)n1 * DCOL;

    // tail loads in flight early: lanes 0-4 -> node0, lanes 5-9 -> node1
    float tail = 0.f;
    if (lane < 5)            tail = rowA[896 + lane];
    else if (lane < 10 && has1) tail = rowB[896 + lane - 5];

    float a0[8] = {0,0,0,0,0,0,0,0};
    float a1[8] = {0,0,0,0,0,0,0,0};
    #pragma unroll
    for (int it = 0; it < 4; it++) {
        int k = lane + it * 32;
        float xf0 = rowA[k];
        float xb0 = rowA[FEAT + k];
        float xf1 = has1 ? rowB[k] : 0.f;
        float xb1 = has1 ? rowB[FEAT + k] : 0.f;
        a0[0] += xf0 * sW[0][k]; a0[1] += xf0 * sW[1][k];
        a0[2] += xf0 * sW[2][k]; a0[3] += xf0 * sW[3][k];
        a0[4] += xb0 * sW[4][k]; a0[5] += xb0 * sW[5][k];
        a0[6] += xb0 * sW[6][k]; a0[7] += xb0 * sW[7][k];
        a1[0] += xf1 * sW[0][k]; a1[1] += xf1 * sW[1][k];
        a1[2] += xf1 * sW[2][k]; a1[3] += xf1 * sW[3][k];
        a1[4] += xb1 * sW[4][k]; a1[5] += xb1 * sW[5][k];
        a1[6] += xb1 * sW[6][k]; a1[7] += xb1 * sW[7][k];
    }
    #pragma unroll
    for (int off = 16; off > 0; off >>= 1) {
        #pragma unroll
        for (int v = 0; v < 8; v++) {
            a0[v] += __shfl_xor_sync(0xffffffffu, a0[v], off);
            a1[v] += __shfl_xor_sync(0xffffffffu, a1[v], off);
        }
    }
    // broadcast both tails to all lanes
    float ta[5], tb[5];
    #pragma unroll
    for (int j = 0; j < 5; j++) {
        ta[j] = __shfl_sync(0xffffffffu, tail, j);
        tb[j] = __shfl_sync(0xffffffffu, tail, 5 + j);
    }
    // lane 0 finishes node0, lane 16 finishes node1 (a1 is fully reduced on all lanes)
    if (lane == 0 || (lane == 16 && has1)) {
        int node = (lane == 0) ? n0 : n1;
        float* acc = (lane == 0) ? a0 : a1;
        float* tl  = (lane == 0) ? ta : tb;
        int idx = (int)tl[4] - 1;
        idx = idx < 0 ? 0 : (idx > 2 ? 2 : idx);
        float val[8];
        #pragma unroll
        for (int v = 0; v < 8; v++) {
            val[v] = acc[v] + g_cst[v] + g_spk[v][idx]
                   + tl[0] * g_spa[v][0] + tl[1] * g_spa[v][1]
                   + tl[2] * g_spa[v][2] + tl[3] * g_spa[v][3];
        }
        g_a[node] = make_float4(val[0], val[1], val[4], val[5]);
        g_b[node] = make_float4(val[2], val[3], val[6], val[7]);
    }
}

__device__ __forceinline__ unsigned f2key(float f)
{
    unsigned u = __float_as_uint(f);
    return (u & 0x80000000u) ? ~u : (u | 0x80000000u);
}
__device__ __forceinline__ float key2f(unsigned k)
{
    unsigned u = (k & 0x80000000u) ? (k ^ 0x80000000u) : ~k;
    return __uint_as_float(u);
}

// 4 edges/thread, vectorized index loads, all random L2 loads issued before
// any atomic. Check-before-atomic is race-safe (keys monotone non-decreasing).
__global__ void __launch_bounds__(256) edge_kernel(const int* __restrict__ ei,
                                                   const int* __restrict__ ea, int E)
{
    int i = blockIdx.x * blockDim.x + threadIdx.x;
    int e = 4 * i;
    if (e >= E) return;

    int s[4], d[4], at[4];
    if (e + 3 < E) {
        int4 s4 = *reinterpret_cast<const int4*>(ei + e);
        int4 d4 = *reinterpret_cast<const int4*>(ei + E + e);
        int4 a4 = *reinterpret_cast<const int4*>(ea + e);
        s[0]=s4.x; s[1]=s4.y; s[2]=s4.z; s[3]=s4.w;
        d[0]=d4.x; d[1]=d4.y; d[2]=d4.z; d[3]=d4.w;
        at[0]=a4.x; at[1]=a4.y; at[2]=a4.z; at[3]=a4.w;
    } else {
        #pragma unroll
        for (int j = 0; j < 4; j++) {
            if (e + j < E) { s[j]=ei[e+j]; d[j]=ei[E+e+j]; at[j]=ea[e+j]; }
            else           { s[j]=0; d[j]=0; at[j]=-1; }
        }
    }

    bool v[4];
    float4 b[4];
    uint4  c[4];
    #pragma unroll
    for (int j = 0; j < 4; j++)
        v[j] = (at[j] == 111) | (at[j] == 0);
    #pragma unroll
    for (int j = 0; j < 4; j++) {
        if (v[j]) { b[j] = g_b[s[j]]; c[j] = g_key[d[j]]; }
    }
    #pragma unroll
    for (int j = 0; j < 4; j++) {
        if (v[j]) {
            unsigned* kp = (unsigned*)&g_key[d[j]];
            unsigned k;
            k = f2key(b[j].x); if (k > c[j].x) atomicMax(kp + 0, k);
            k = f2key(b[j].y); if (k > c[j].y) atomicMax(kp + 1, k);
            k = f2key(b[j].z); if (k > c[j].z) atomicMax(kp + 2, k);
            k = f2key(b[j].w); if (k > c[j].w) atomicMax(kp + 3, k);
        }
    }
}

__global__ void __launch_bounds__(512) final_kernel(float* __restrict__ out, int N)
{
    int half = (N + 1) >> 1;
    int i = blockIdx.x * blockDim.x + threadIdx.x;
    #pragma unroll
    for (int r = 0; r < 2; r++) {
        int n = i + r * half;
        if (n >= N || i >= half) continue;
        uint4 k = g_key[n];
        float4 a = g_a[n];
        float o0 = 0.f, o1 = 0.f;
        if (k.x) o0 += a.x + key2f(k.x);
        if (k.z) o0 += a.z + key2f(k.z);
        if (k.y) o1 += a.y + key2f(k.y);
        if (k.w) o1 += a.w + key2f(k.w);
        out[n * 2 + 0] = o0;
        out[n * 2 + 1] = o1;
    }
}

extern "C" void kernel_launch(void* const* d_in, const int* in_sizes, int n_in,
                              void* d_out, int out_size)
{
    const float* x         = (const float*)d_in[0];
    const int*   ei        = (const int*)d_in[1];
    const int*   ea        = (const int*)d_in[2];
    const float* speaker_w = (const float*)d_in[3];
    const float* speaker_b = (const float*)d_in[4];
    const float* spatial_w = (const float*)d_in[5];
    const float* spatial_b = (const float*)d_in[6];
    const float* f1_w = (const float*)d_in[7];
    const float* f1_b = (const float*)d_in[8];
    const float* f2_w = (const float*)d_in[9];
    const float* f2_b = (const float*)d_in[10];
    const float* fe_w = (const float*)d_in[11];
    const float* fe_b = (const float*)d_in[12];
    const float* g1_w = (const float*)d_in[13];
    const float* g1_b = (const float*)d_in[14];
    const float* g2_w = (const float*)d_in[15];
    const float* g2_b = (const float*)d_in[16];
    const float* ge_w = (const float*)d_in[17];
    const float* ge_b = (const float*)d_in[18];

    int N = in_sizes[0] / DCOL;
    int E = in_sizes[2];

    precompute_kernel<<<8, 512>>>(f1_w, f1_b, f2_w, f2_b, fe_w, fe_b,
                                  g1_w, g1_b, g2_w, g2_b, ge_w, ge_b,
                                  speaker_w, speaker_b, spatial_w, spatial_b);
    node_kernel<<<(N + 31) / 32, 512>>>(x, N);
    int quads = (E + 3) / 4;
    edge_kernel<<<(quads + 255) / 256, 256>>>(ei, ea, E);
    int half = (N + 1) / 2;
    final_kernel<<<(half + 511) / 512, 512>>>((float*)d_out, N);
}

// round 8
// speedup vs baseline: 1.5899x; 1.0899x over previous
#include <cuda_runtime.h>
#include <cstdint>

#define DCOL   901
#define NMAX   50048
#define FEAT   128

__device__ float  g_w128[8][128];
__device__ float  g_spa[8][4];
__device__ float  g_spk[8][3];
__device__ float  g_cst[8];
__device__ float4 g_a[NMAX];
__device__ float4 g_b[NMAX];
__device__ uint4  g_key[NMAX];

// vec index v: body=v>>2, kind=(v>>1)&1 (0=a dst-side, 1=b src-side), c=v&1
__global__ void precompute_kernel(
    const float* __restrict__ f1_w, const float* __restrict__ f1_b,
    const float* __restrict__ f2_w, const float* __restrict__ f2_b,
    const float* __restrict__ fe_w, const float* __restrict__ fe_b,
    const float* __restrict__ g1_w, const float* __restrict__ g1_b,
    const float* __restrict__ g2_w, const float* __restrict__ g2_b,
    const float* __restrict__ ge_w, const float* __restrict__ ge_b,
    const float* __restrict__ speaker_w, const float* __restrict__ speaker_b,
    const float* __restrict__ spatial_w, const float* __restrict__ spatial_b)
{
    int v = blockIdx.x;
    int body = v >> 2;
    int kind = (v >> 1) & 1;
    int c = v & 1;
    const float* W1 = body ? g1_w : f1_w;
    const float* B1 = body ? g1_b : f1_b;
    const float* W2 = body ? g2_w : f2_w;
    const float* B2 = body ? g2_b : f2_b;
    const float* EW = body ? ge_w : fe_w;
    const float* EB = body ? ge_b : fe_b;

    __shared__ float u[64], Su[16], Pu[16];
    int t = threadIdx.x;
    int warp = t >> 5, lane = t & 31;
    if (t < 64) {
        float lo = EW[t * 2 + c];
        float hi = EW[(64 + t) * 2 + c];
        u[t] = kind ? hi : (lo - hi);
    }
    __syncthreads();

    #pragma unroll
    for (int j = 0; j < 10; j++) {
        int r = warp + 16 * j;
        int k0 = lane, k1 = lane + 32;
        float s;
        if (r < 128) {
            s = (W1[r * 64 + k0] + W2[r * 64 + k0]) * u[k0]
              + (W1[r * 64 + k1] + W2[r * 64 + k1]) * u[k1];
        } else {
            s = W2[r * 64 + k0] * u[k0] + W2[r * 64 + k1] * u[k1];
        }
        #pragma unroll
        for (int off = 16; off > 0; off >>= 1)
            s += __shfl_xor_sync(0xffffffffu, s, off);
        if (lane == 0) {
            if (r < 128)      g_w128[v][r] = s;
            else if (r < 144) Su[r - 128] = s;
            else              Pu[r - 144] = s;
        }
    }
    __syncthreads();

    if (t < 4) {
        float s = 0.f;
        for (int m = 0; m < 16; m++) s += spatial_w[t * 16 + m] * Pu[m];
        g_spa[v][t] = s;
    } else if (t < 7) {
        int r = t - 4;
        float s = 0.f;
        for (int m = 0; m < 16; m++) s += speaker_w[r * 16 + m] * Su[m];
        g_spk[v][r] = s;
    } else if (t == 7) {
        float s = 0.f;
        for (int k = 0; k < 64; k++) s += (B1[k] + B2[k]) * u[k];
        for (int m = 0; m < 16; m++) s += speaker_b[m] * Su[m] + spatial_b[m] * Pu[m];
        if (kind == 0) s += EB[c];
        g_cst[v] = s;
    }
}

// 512 threads = 16 warps; each warp processes 4 nodes (64 nodes/block).
// Half-warp split: lanes 0-15 accumulate the 4 face vectors, lanes 16-31 the
// 4 body vectors. Also zeroes g_key.
__global__ void __launch_bounds__(512) node_kernel(const float* __restrict__ x, int N)
{
    __shared__ float sW[8][128];
    __shared__ float sAux[64];   // [0..31]=spa(v*4+j)  [32..55]=spk(v*3+r)  [56..63]=cst
    int t = threadIdx.x;
    #pragma unroll
    for (int i = t; i < 1024; i += 512)
        sW[i >> 7][i & 127] = g_w128[i >> 7][i & 127];
    if (t < 32)       sAux[t] = g_spa[t >> 2][t & 3];
    else if (t < 56)  sAux[t] = g_spk[(t - 32) / 3][(t - 32) % 3];
    else if (t < 64)  sAux[t] = g_cst[t - 56];
    __syncthreads();

    int warp = t >> 5, lane = t & 31;
    int half = lane >> 4;         // 0 = face, 1 = body
    int l = lane & 15;
    int base = blockIdx.x * 64 + warp * 4;

    bool has[4];
    const float* rp[4];
    #pragma unroll
    for (int m = 0; m < 4; m++) {
        has[m] = (base + m) < N;
        rp[m] = x + (size_t)(base + m) * DCOL + half * 128;
    }
    if (lane < 4 && has[lane])
        g_key[base + lane] = make_uint4(0u, 0u, 0u, 0u);

    // tail: lanes 0..19 load node (lane/5), value row[896 + lane%5]
    float tail = 0.f;
    if (lane < 20) {
        int m = lane / 5, off = lane % 5;
        if (has[m]) tail = x[(size_t)(base + m) * DCOL + 896 + off];
    }

    float acc[4][4] = {{0,0,0,0},{0,0,0,0},{0,0,0,0},{0,0,0,0}};
    #pragma unroll
    for (int it = 0; it < 8; it++) {
        int k = l + 16 * it;
        float xv[4];
        #pragma unroll
        for (int m = 0; m < 4; m++)
            xv[m] = has[m] ? rp[m][k] : 0.f;
        float w0 = sW[half * 4 + 0][k], w1 = sW[half * 4 + 1][k];
        float w2 = sW[half * 4 + 2][k], w3 = sW[half * 4 + 3][k];
        #pragma unroll
        for (int m = 0; m < 4; m++) {
            acc[m][0] += xv[m] * w0; acc[m][1] += xv[m] * w1;
            acc[m][2] += xv[m] * w2; acc[m][3] += xv[m] * w3;
        }
    }
    // reduce within each 16-lane half
    #pragma unroll
    for (int off = 8; off > 0; off >>= 1) {
        #pragma unroll
        for (int m = 0; m < 4; m++) {
            #pragma unroll
            for (int v = 0; v < 4; v++)
                acc[m][v] += __shfl_xor_sync(0xffffffffu, acc[m][v], off);
        }
    }
    // broadcast tails
    float tl[4][5];
    #pragma unroll
    for (int m = 0; m < 4; m++) {
        #pragma unroll
        for (int j = 0; j < 5; j++)
            tl[m][j] = __shfl_sync(0xffffffffu, tail, m * 5 + j);
    }
    // epilogue on all lanes (each half uses its own 4 vecs vh = half*4 + v)
    #pragma unroll
    for (int m = 0; m < 4; m++) {
        int idx = (int)tl[m][4] - 1;
        idx = idx < 0 ? 0 : (idx > 2 ? 2 : idx);
        float val[4];
        #pragma unroll
        for (int v = 0; v < 4; v++) {
            int vh = half * 4 + v;
            val[v] = acc[m][v] + sAux[56 + vh] + sAux[32 + vh * 3 + idx]
                   + tl[m][0] * sAux[vh * 4 + 0] + tl[m][1] * sAux[vh * 4 + 1]
                   + tl[m][2] * sAux[vh * 4 + 2] + tl[m][3] * sAux[vh * 4 + 3];
        }
        // cross-half exchange: partner's val[0..3]
        float p0 = __shfl_xor_sync(0xffffffffu, val[0], 16);
        float p1 = __shfl_xor_sync(0xffffffffu, val[1], 16);
        float p2 = __shfl_xor_sync(0xffffffffu, val[2], 16);
        float p3 = __shfl_xor_sync(0xffffffffu, val[3], 16);
        if (has[m]) {
            if (lane == 0)       // face lane: own a0,a1 + body a0,a1 from lane16
                g_a[base + m] = make_float4(val[0], val[1], p0, p1);
            else if (lane == 16) // body lane: face b0,b1 from lane0 + own b0,b1
                g_b[base + m] = make_float4(p2, p3, val[2], val[3]);
        }
    }
}

__device__ __forceinline__ unsigned f2key(float f)
{
    unsigned u = __float_as_uint(f);
    return (u & 0x80000000u) ? ~u : (u | 0x80000000u);
}
__device__ __forceinline__ float key2f(unsigned k)
{
    unsigned u = (k & 0x80000000u) ? (k ^ 0x80000000u) : ~k;
    return __uint_as_float(u);
}

// 4 edges/thread, vectorized index loads, all random L2 loads issued before
// any atomic. Check-before-atomic is race-safe (keys monotone non-decreasing).
__global__ void __launch_bounds__(256) edge_kernel(const int* __restrict__ ei,
                                                   const int* __restrict__ ea, int E)
{
    int i = blockIdx.x * blockDim.x + threadIdx.x;
    int e = 4 * i;
    if (e >= E) return;

    int s[4], d[4], at[4];
    if (e + 3 < E) {
        int4 s4 = *reinterpret_cast<const int4*>(ei + e);
        int4 d4 = *reinterpret_cast<const int4*>(ei + E + e);
        int4 a4 = *reinterpret_cast<const int4*>(ea + e);
        s[0]=s4.x; s[1]=s4.y; s[2]=s4.z; s[3]=s4.w;
        d[0]=d4.x; d[1]=d4.y; d[2]=d4.z; d[3]=d4.w;
        at[0]=a4.x; at[1]=a4.y; at[2]=a4.z; at[3]=a4.w;
    } else {
        #pragma unroll
        for (int j = 0; j < 4; j++) {
            if (e + j < E) { s[j]=ei[e+j]; d[j]=ei[E+e+j]; at[j]=ea[e+j]; }
            else           { s[j]=0; d[j]=0; at[j]=-1; }
        }
    }

    bool v[4];
    float4 b[4];
    uint4  c[4];
    #pragma unroll
    for (int j = 0; j < 4; j++)
        v[j] = (at[j] == 111) | (at[j] == 0);
    #pragma unroll
    for (int j = 0; j < 4; j++) {
        if (v[j]) { b[j] = g_b[s[j]]; c[j] = g_key[d[j]]; }
    }
    #pragma unroll
    for (int j = 0; j < 4; j++) {
        if (v[j]) {
            unsigned* kp = (unsigned*)&g_key[d[j]];
            unsigned k;
            k = f2key(b[j].x); if (k > c[j].x) atomicMax(kp + 0, k);
            k = f2key(b[j].y); if (k > c[j].y) atomicMax(kp + 1, k);
            k = f2key(b[j].z); if (k > c[j].z) atomicMax(kp + 2, k);
            k = f2key(b[j].w); if (k > c[j].w) atomicMax(kp + 3, k);
        }
    }
}

// 1 node per thread, 50K threads: maximize latency hiding on L2-resident data.
__global__ void __launch_bounds__(256) final_kernel(float* __restrict__ out, int N)
{
    int n = blockIdx.x * blockDim.x + threadIdx.x;
    if (n >= N) return;
    uint4 k = g_key[n];
    float4 a = g_a[n];
    float o0 = 0.f, o1 = 0.f;
    if (k.x) o0 += a.x + key2f(k.x);
    if (k.z) o0 += a.z + key2f(k.z);
    if (k.y) o1 += a.y + key2f(k.y);
    if (k.w) o1 += a.w + key2f(k.w);
    reinterpret_cast<float2*>(out)[n] = make_float2(o0, o1);
}

extern "C" void kernel_launch(void* const* d_in, const int* in_sizes, int n_in,
                              void* d_out, int out_size)
{
    const float* x         = (const float*)d_in[0];
    const int*   ei        = (const int*)d_in[1];
    const int*   ea        = (const int*)d_in[2];
    const float* speaker_w = (const float*)d_in[3];
    const float* speaker_b = (const float*)d_in[4];
    const float* spatial_w = (const float*)d_in[5];
    const float* spatial_b = (const float*)d_in[6];
    const float* f1_w = (const float*)d_in[7];
    const float* f1_b = (const float*)d_in[8];
    const float* f2_w = (const float*)d_in[9];
    const float* f2_b = (const float*)d_in[10];
    const float* fe_w = (const float*)d_in[11];
    const float* fe_b = (const float*)d_in[12];
    const float* g1_w = (const float*)d_in[13];
    const float* g1_b = (const float*)d_in[14];
    const float* g2_w = (const float*)d_in[15];
    const float* g2_b = (const float*)d_in[16];
    const float* ge_w = (const float*)d_in[17];
    const float* ge_b = (const float*)d_in[18];

    int N = in_sizes[0] / DCOL;
    int E = in_sizes[2];

    precompute_kernel<<<8, 512>>>(f1_w, f1_b, f2_w, f2_b, fe_w, fe_b,
                                  g1_w, g1_b, g2_w, g2_b, ge_w, ge_b,
                                  speaker_w, speaker_b, spatial_w, spatial_b);
    node_kernel<<<(N + 63) / 64, 512>>>(x, N);
    int quads = (E + 3) / 4;
    edge_kernel<<<(quads + 255) / 256, 256>>>(ei, ea, E);
    final_kernel<<<(N + 255) / 256, 256>>>((float*)d_out, N);
}